// round 2
// baseline (speedup 1.0000x reference)
#include <cuda_runtime.h>

// Shapes (fixed by the problem)
#define B_  32
#define C_  256
#define HW4 784                       // (56*56)/4 float4 per plane
#define TOTAL4 (2 * B_ * C_ * HW4)    // 12,845,056 float4 total output
#define CP_T 256
#define CP_U 4
#define CP_B (TOTAL4 / (CP_T * CP_U)) // 12544, exact

// Packed channel map: g_map[which][c] = srcChan | (sel << 8); sel=1 -> x2
__device__ int g_map[2][C_];

// ---------------------------------------------------------------------------
// Kernel A: 512 threads, one (channel, array) pair per thread.
//   rank = stable descending rank of |w| (ties by ascending index)
//   order[rank] = c ;  cumsum(below) via ballot ;  gather cross maps.
// Ends with PDL trigger so the copy kernel can overlap its prologue.
// ---------------------------------------------------------------------------
__global__ void build_map(const float* __restrict__ w1,
                          const float* __restrict__ w2,
                          const float* __restrict__ thr_p) {
    __shared__ float a[2][C_];
    __shared__ int   order[2][C_];
    __shared__ int   warpcnt[2][8];
    __shared__ int   rankbuf[2][C_];
    __shared__ int   belbuf[2][C_];

    const int tid = threadIdx.x;
    const int c   = tid & (C_ - 1);
    const int arr = tid >> 8;          // 0 -> w1, 1 -> w2
    const float thr = thr_p[0];

    if (arr == 0) {                    // 256 threads load both arrays
        a[0][c] = fabsf(w1[c]);
        a[1][c] = fabsf(w2[c]);
    }
    __syncthreads();

    const float v = a[arr][c];

    // Stable descending rank via counting, float4-vectorized smem reads
    int r = 0;
    const float4* av = (const float4*)a[arr];
#pragma unroll 4
    for (int j4 = 0; j4 < C_ / 4; j4++) {
        const float4 q = av[j4];
        const int j = j4 * 4;
        r += (q.x > v) || (q.x == v && (j + 0) < c);
        r += (q.y > v) || (q.y == v && (j + 1) < c);
        r += (q.z > v) || (q.z == v && (j + 2) < c);
        r += (q.w > v) || (q.w == v && (j + 3) < c);
    }
    order[arr][r] = c;

    // below + inclusive prefix count via ballot
    const int below = (v < thr) ? 1 : 0;
    const unsigned m    = __ballot_sync(0xffffffffu, below);
    const int      lane = c & 31;
    const int      warp = c >> 5;
    const int incl = __popc(m & (0xffffffffu >> (31 - lane)));
    if (lane == 31) warpcnt[arr][warp] = __popc(m);
    __syncthreads();

    int pre = 0;
    for (int wi = 0; wi < warp; wi++) pre += warpcnt[arr][wi];
    rankbuf[arr][c] = max(pre + incl - 1, 0);
    belbuf[arr][c]  = below;
    __syncthreads();

    if (arr == 0) {
        // feature1[:,c] = below1 ? x2[:, order2[rank1]] : x1[:, c]
        const int s1 = order[1][rankbuf[0][c]];
        g_map[0][c] = belbuf[0][c] ? (s1 | (1 << 8)) : c;
        // feature2[:,c] = below2 ? x1[:, order1[rank2]] : x2[:, c]
        const int s2 = order[0][rankbuf[1][c]];
        g_map[1][c] = belbuf[1][c] ? s2 : (c | (1 << 8));
    }
    __threadfence();
    __syncthreads();
    cudaTriggerProgrammaticLaunchCompletion();
}

// ---------------------------------------------------------------------------
// Kernel B: HBM-bound gather-copy (unchanged structure from the 59.2us
// version). PDL: all map-independent index math happens before
// cudaGridDependencySynchronize().
// ---------------------------------------------------------------------------
__global__ __launch_bounds__(CP_T)
void exchange_copy(const float4* __restrict__ x1,
                   const float4* __restrict__ x2,
                   float4* __restrict__ out) {
    const unsigned base = blockIdx.x * (CP_T * CP_U) + threadIdx.x;

    unsigned idx[CP_U], p[CP_U], hw[CP_U];
#pragma unroll
    for (int k = 0; k < CP_U; k++) {
        idx[k] = base + k * CP_T;            // < TOTAL4, exact
        p[k]   = idx[k] / HW4;               // plane id [0, 2*B*C)
        hw[k]  = idx[k] - p[k] * HW4;        // float4 offset in plane
    }

    cudaGridDependencySynchronize();         // wait for build_map's trigger

    float4 v[CP_U];
#pragma unroll
    for (int k = 0; k < CP_U; k++) {
        const unsigned which = p[k] >> 13;          // B*C = 8192
        const unsigned c     = p[k] & (C_ - 1);
        const unsigned b     = (p[k] >> 8) & (B_ - 1);
        const int mv = g_map[which][c];
        const float4* __restrict__ src = (mv & 256) ? x2 : x1;
        const unsigned sc = mv & 255;
        v[k] = src[(b * C_ + sc) * HW4 + hw[k]];
    }
#pragma unroll
    for (int k = 0; k < CP_U; k++) out[idx[k]] = v[k];
}

extern "C" void kernel_launch(void* const* d_in, const int* in_sizes, int n_in,
                              void* d_out, int out_size) {
    const float* x1  = (const float*)d_in[0];
    const float* x2  = (const float*)d_in[1];
    const float* w1  = (const float*)d_in[2];
    const float* w2  = (const float*)d_in[3];
    const float* thr = (const float*)d_in[4];

    build_map<<<1, 512>>>(w1, w2, thr);

    cudaLaunchConfig_t cfg = {};
    cfg.gridDim  = dim3(CP_B);
    cfg.blockDim = dim3(CP_T);
    cfg.dynamicSmemBytes = 0;
    cfg.stream = 0;
    cudaLaunchAttribute at[1];
    at[0].id = cudaLaunchAttributeProgrammaticStreamSerialization;
    at[0].val.programmaticStreamSerializationAllowed = 1;
    cfg.attrs = at;
    cfg.numAttrs = 1;
    cudaLaunchKernelEx(&cfg, exchange_copy,
                       (const float4*)x1, (const float4*)x2, (float4*)d_out);
}